// round 15
// baseline (speedup 1.0000x reference)
#include <cuda_runtime.h>
#include <cuda_bf16.h>
#include <mma.h>
#include <math.h>

using namespace nvcuda;

#define B_TOT 16384
#define S_DIM 300
#define A_DIM 30
#define M_PROTO 16
#define NT 256
#define ROWS 16
#define NBLK (B_TOT / ROWS)
#define DH 260
#define LDA 312      // A row stride (624B = 39*16B, odd -> conflict-free LDSM)
#define LDB 264      // W1 chunk stride (528B = 33*16B)
#define LDH 264      // h stride
#define LDG2 136     // G chunk stride (272B = 17*16B)
#define BCH (16 * LDB)
#define GCH (16 * LDG2)

// batch-independent tables
__device__ float c_g[128];
__device__ float conc_g[M_PROTO * A_DIM];
__device__ __align__(16) __nv_bfloat16 W1hi_g[304 * 256];
__device__ __align__(16) __nv_bfloat16 W1lo_g[304 * 256];
__device__ __align__(16) __nv_bfloat16 Ghi_g[256 * 128];
__device__ __align__(16) __nv_bfloat16 Glo_g[256 * 128];

// ---------------------------------------------------------------------------
// Precompute: blocks 0..63 -> 4 G rows each (bf16 split written inline);
//             64 -> c_g; 65..80 -> conc_g[m]
// ---------------------------------------------------------------------------
__global__ void __launch_bounds__(256) precompute_kernel(
    const float* __restrict__ pk, const float* __restrict__ enc_W2,
    const float* __restrict__ enc_b2, const float* __restrict__ dW1,
    const float* __restrict__ db1, const float* __restrict__ dW2,
    const float* __restrict__ db2) {
    const int bk = blockIdx.x;
    const int t = threadIdx.x;
    if (bk < 64) {
        __shared__ float w2rows[4 * 2048];
        __shared__ float pks[16 * 257];
        __shared__ float part[256];
        for (int i = t; i < 4 * 2048; i += 256)
            w2rows[i] = enc_W2[bk * 8192 + i];
        for (int i = t; i < 4096; i += 256)
            pks[(i >> 8) * 257 + (i & 255)] = pk[i];
        __syncthreads();
        const int mn = t & 127, half = t >> 7;
        const int m = mn >> 4, n = mn & 15;
        const float* pr = pks + n * 257 + half * 128;
        #pragma unroll
        for (int rr = 0; rr < 4; rr++) {
            const float* wr = w2rows + rr * 2048 + m * 256 + half * 128;
            float s = 0.f;
            #pragma unroll 8
            for (int e = 0; e < 128; e++) s += wr[e] * pr[e];
            part[t] = s;
            __syncthreads();
            if (t < 128) {
                const float g = (part[t] + part[t + 128]) * 0.0625f;
                const int k = bk * 4 + rr;
                const __nv_bfloat16 hi = __float2bfloat16(g);
                Ghi_g[k * 128 + t] = hi;
                Glo_g[k * 128 + t] = __float2bfloat16(g - __bfloat162float(hi));
            }
            __syncthreads();
        }
    } else if (bk == 64) {
        __shared__ float part[256];
        const int mn = t & 127, half = t >> 7;
        const int m = mn >> 4, n = mn & 15;
        const float4* br = (const float4*)(enc_b2 + m * 256 + half * 128);
        const float4* pr = (const float4*)(pk + n * 256 + half * 128);
        float s = 0.f;
        #pragma unroll 8
        for (int e = 0; e < 32; e++) {
            const float4 b4 = __ldg(&br[e]);
            const float4 p4 = __ldg(&pr[e]);
            s += b4.x * p4.x + b4.y * p4.y + b4.z * p4.z + b4.w * p4.w;
        }
        part[t] = s;
        __syncthreads();
        if (t < 128) c_g[t] = (part[t] + part[t + 128]) * 0.0625f;
    } else {
        const int m = bk - 65;
        __shared__ float part[256];
        __shared__ float hd[128];
        const int h = t & 127, eh = t >> 7;
        const float* pkm = pk + m * 256 + eh * 128;
        const float* wcol = dW1 + (m * 256 + eh * 128) * 128 + h;
        float s = 0.f;
        #pragma unroll 8
        for (int e = 0; e < 128; e++) s += pkm[e] * wcol[e * 128];
        part[t] = s;
        __syncthreads();
        if (t < 128)
            hd[t] = fmaxf(part[t] + part[t + 128] + db1[m * 128 + t], 0.f);
        __syncthreads();
        if (t < A_DIM) {
            float s2 = db2[m * A_DIM + t];
            const float* w2 = dW2 + m * 128 * A_DIM + t;
            #pragma unroll 8
            for (int h2 = 0; h2 < 128; h2++)
                s2 += hd[h2] * __ldg(w2 + h2 * A_DIM);
            conc_g[m * A_DIM + t] = fmaxf(s2, 0.f) + log1pf(expf(-fabsf(s2)));
        }
    }
}

// ---------------------------------------------------------------------------
// Convert: W1 bf16 hi/lo split only (K padded 300->304)
// ---------------------------------------------------------------------------
__global__ void __launch_bounds__(256) convert_kernel(const float* __restrict__ W1) {
    const int idx = blockIdx.x * 256 + threadIdx.x;
    const int k = idx >> 8;
    const float w = (k < 300) ? W1[idx] : 0.f;
    const __nv_bfloat16 hi = __float2bfloat16(w);
    W1hi_g[idx] = hi;
    W1lo_g[idx] = __float2bfloat16(w - __bfloat162float(hi));
}

// ---------------------------------------------------------------------------
// Main kernel: 1024 blocks x 256 threads, 16 batch rows/block.
// wmma bf16 hi/lo, padded strides, single-bar pipelined double buffering.
// ---------------------------------------------------------------------------
__global__ void __launch_bounds__(NT, 2) main_kernel(
    const float* __restrict__ state, const float* __restrict__ fitness,
    const float* __restrict__ pk, const float* __restrict__ b1,
    const float* __restrict__ ln_g, const float* __restrict__ ln_b,
    const float* __restrict__ tc_W, const float* __restrict__ tc_b,
    const float* __restrict__ tc_cW, const float* __restrict__ tc_cb,
    const float* __restrict__ w_prev, float* __restrict__ out) {
    extern __shared__ char smraw[];
    float* st          = (float*)smraw;                    // 4800 f
    float* dh          = (float*)(smraw + 19200);          // 16x260 f
    __nv_bfloat16* Ahi = (__nv_bfloat16*)(smraw + 35840);  // 16xLDA
    __nv_bfloat16* Alo = (__nv_bfloat16*)(smraw + 45824);
    __nv_bfloat16* Bhi = (__nv_bfloat16*)(smraw + 55808);  // 2xBCH
    __nv_bfloat16* Blo = (__nv_bfloat16*)(smraw + 72704);
    float* dds         = (float*)(smraw + 89600);          // 256 f
    float* concs       = (float*)(smraw + 90624);          // 480 f
    float* stats       = (float*)(smraw + 92544);          // 48 f
    float* lgt         = st;
    __nv_bfloat16* hhi = Ahi;
    __nv_bfloat16* hlo = Alo;

    const int tid = threadIdx.x;
    const int lane = tid & 31;
    const int wid = tid >> 5;
    const int b0 = blockIdx.x * ROWS;
    const unsigned FULL = 0xffffffffu;

    // ---- cooperative loads ----
    {
        const float4* gsrc = (const float4*)(state + (size_t)b0 * S_DIM);
        float4* sdst = (float4*)st;
        for (int i = tid; i < 1200; i += NT) sdst[i] = gsrc[i];
        for (int i = tid; i < M_PROTO * A_DIM; i += NT) concs[i] = conc_g[i];
    }
    __syncthreads();

    // ---- A split into bf16 hi/lo ----
    for (int i = tid; i < 16 * LDA; i += NT) {
        const int r = i / LDA, k = i - r * LDA;
        const float v = (k < 300) ? st[r * 300 + k] : 0.f;
        const __nv_bfloat16 hi = __float2bfloat16(v);
        Ahi[i] = hi;
        Alo[i] = __float2bfloat16(v - __bfloat162float(hi));
    }

    // ---- stage 1: market features + danger + crisis ----
    {
        const int rA = wid, rB = wid + 8;
        const float* sA = st + rA * S_DIM;
        const float* sB = st + rB * S_DIM;
        float mfa[12], mfb[12];
        #pragma unroll
        for (int pass = 0; pass < 2; pass++) {
            const float* srow = pass ? sB : sA;
            float* mf = pass ? mfb : mfa;
            float p = 0.f, sh = 0.f;
            if (lane < 30) { p = srow[1 + lane]; sh = srow[31 + lane]; }
            float sp = p, spp = p * p, sps = p * sh;
            #pragma unroll
            for (int m2 = 16; m2 >= 1; m2 >>= 1) {
                sp  += __shfl_xor_sync(FULL, sp, m2);
                spp += __shfl_xor_sync(FULL, spp, m2);
                sps += __shfl_xor_sync(FULL, sps, m2);
            }
            const float bal = srow[0];
            const float mean = sp * (1.f / 30.f);
            const float var = fmaxf((spp - 30.f * mean * mean) * (1.f / 29.f), 0.f);
            mf[0] = bal; mf[1] = mean;
            mf[2] = sqrtf(var) + 1e-8f;
            mf[3] = bal / (bal + sps + 1e-8f);
            #pragma unroll
            for (int i = 0; i < 8; i++) mf[4 + i] = srow[61 + 30 * i];
        }
        float cpA = 0.f, cpB = 0.f;
        #pragma unroll
        for (int i = 0; i < 8; i++) {
            const int j = lane + 32 * i;
            const float bj = tc_b[j];
            float aA = bj, aB = bj;
            #pragma unroll
            for (int f = 0; f < 12; f++) {
                const float w = tc_W[f * 256 + j];
                aA += mfa[f] * w; aB += mfb[f] * w;
            }
            const float dA = tanhf(aA), dB = tanhf(aB);
            dh[rA * DH + j] = dA;
            dh[rB * DH + j] = dB;
            const float cw = tc_cW[j];
            cpA += dA * cw; cpB += dB * cw;
        }
        #pragma unroll
        for (int m2 = 16; m2 >= 1; m2 >>= 1) {
            cpA += __shfl_xor_sync(FULL, cpA, m2);
            cpB += __shfl_xor_sync(FULL, cpB, m2);
        }
        if (lane == 0) {
            const float cb = tc_cb[0];
            stats[32 + rA] = 1.f / (1.f + expf(-(cpA + cb)));
            stats[32 + rB] = 1.f / (1.f + expf(-(cpB + cb)));
        }
    }
    __syncthreads();

    // ---- dd[r][n] (fp32 exact) + W1 chunk-0 staging ----
    {
        const int n = tid >> 4, kq = tid & 15;
        float pkc[16];
        {
            const float4* pr = (const float4*)(pk + n * 256 + kq * 16);
            #pragma unroll
            for (int i = 0; i < 4; i++) {
                const float4 p4 = __ldg(&pr[i]);
                pkc[i * 4 + 0] = p4.x; pkc[i * 4 + 1] = p4.y;
                pkc[i * 4 + 2] = p4.z; pkc[i * 4 + 3] = p4.w;
            }
        }
        #pragma unroll 4
        for (int r = 0; r < ROWS; r++) {
            const float* dr = dh + r * DH + kq * 16;
            float s = 0.f;
            #pragma unroll
            for (int i = 0; i < 4; i++) {
                const float4 d4 = *(const float4*)&dr[i * 4];
                s += d4.x * pkc[i * 4] + d4.y * pkc[i * 4 + 1] +
                     d4.z * pkc[i * 4 + 2] + d4.w * pkc[i * 4 + 3];
            }
            #pragma unroll
            for (int m2 = 8; m2 >= 1; m2 >>= 1) s += __shfl_xor_sync(FULL, s, m2);
            if (kq == 0) dds[r * 16 + n] = s * 0.0625f;
        }
        // stage W1 chunk 0 into buffer 0
        const uint4 h0 = ((const uint4*)W1hi_g)[tid];
        const uint4 h1 = ((const uint4*)W1hi_g)[tid + 256];
        const uint4 l0 = ((const uint4*)W1lo_g)[tid];
        const uint4 l1 = ((const uint4*)W1lo_g)[tid + 256];
        const int r8 = tid >> 5, c8 = tid & 31;
        uint4* bh4 = (uint4*)Bhi;
        uint4* bl4 = (uint4*)Blo;
        bh4[r8 * 33 + c8] = h0; bh4[(r8 + 8) * 33 + c8] = h1;
        bl4[r8 * 33 + c8] = l0; bl4[(r8 + 8) * 33 + c8] = l1;
    }
    __syncthreads();

    // ---- W1 GEMM: 19 k-chunks, single-bar pipelined double buffer ----
    {
        const int n0 = wid * 32;
        const int r8 = tid >> 5, c8 = tid & 31;
        wmma::fragment<wmma::matrix_a, 16, 16, 16, __nv_bfloat16, wmma::row_major> fah, fal;
        wmma::fragment<wmma::matrix_b, 16, 16, 16, __nv_bfloat16, wmma::row_major> fbh0, fbl0, fbh1, fbl1;
        wmma::fragment<wmma::accumulator, 16, 16, 16, float> c0, c1;
        wmma::fill_fragment(c0, 0.f);
        wmma::fill_fragment(c1, 0.f);
        // preload chunk 1 into regs
        uint4 ph0 = ((const uint4*)W1hi_g)[512 + tid];
        uint4 ph1 = ((const uint4*)W1hi_g)[512 + 256 + tid];
        uint4 pl0 = ((const uint4*)W1lo_g)[512 + tid];
        uint4 pl1 = ((const uint4*)W1lo_g)[512 + 256 + tid];
        for (int kc = 0; kc < 19; kc++) {
            const int s = kc & 1;
            if (kc < 18) {   // STS chunk kc+1 (in regs) into buf s^1
                uint4* bh4 = (uint4*)(Bhi + (s ^ 1) * BCH);
                uint4* bl4 = (uint4*)(Blo + (s ^ 1) * BCH);
                bh4[r8 * 33 + c8] = ph0; bh4[(r8 + 8) * 33 + c8] = ph1;
                bl4[r8 * 33 + c8] = pl0; bl4[(r8 + 8) * 33 + c8] = pl1;
            }
            if (kc < 17) {   // LDG chunk kc+2 into regs
                const int base = (kc + 2) * 512;
                ph0 = ((const uint4*)W1hi_g)[base + tid];
                ph1 = ((const uint4*)W1hi_g)[base + 256 + tid];
                pl0 = ((const uint4*)W1lo_g)[base + tid];
                pl1 = ((const uint4*)W1lo_g)[base + 256 + tid];
            }
            const __nv_bfloat16* bsh = Bhi + s * BCH;
            const __nv_bfloat16* bsl = Blo + s * BCH;
            wmma::load_matrix_sync(fah, Ahi + kc * 16, LDA);
            wmma::load_matrix_sync(fal, Alo + kc * 16, LDA);
            wmma::load_matrix_sync(fbh0, bsh + n0, LDB);
            wmma::load_matrix_sync(fbl0, bsl + n0, LDB);
            wmma::load_matrix_sync(fbh1, bsh + n0 + 16, LDB);
            wmma::load_matrix_sync(fbl1, bsl + n0 + 16, LDB);
            wmma::mma_sync(c0, fah, fbh0, c0);
            wmma::mma_sync(c0, fah, fbl0, c0);
            wmma::mma_sync(c0, fal, fbh0, c0);
            wmma::mma_sync(c1, fah, fbh1, c1);
            wmma::mma_sync(c1, fah, fbl1, c1);
            wmma::mma_sync(c1, fal, fbh1, c1);
            __syncthreads();
        }
        wmma::store_matrix_sync(dh + n0, c0, DH, wmma::mem_row_major);
        wmma::store_matrix_sync(dh + n0 + 16, c1, DH, wmma::mem_row_major);
    }
    __syncthreads();

    // ---- layernorm stats (b1 folded at read) ----
    for (int rr = 0; rr < 2; rr++) {
        const int r = wid + rr * 8;
        float s1 = 0.f, s2 = 0.f;
        #pragma unroll
        for (int i = 0; i < 8; i++) {
            const int j = lane + 32 * i;
            const float v = dh[r * DH + j] + b1[j];
            s1 += v; s2 += v * v;
        }
        #pragma unroll
        for (int m2 = 16; m2 >= 1; m2 >>= 1) {
            s1 += __shfl_xor_sync(FULL, s1, m2);
            s2 += __shfl_xor_sync(FULL, s2, m2);
        }
        if (lane == 0) {
            const float mu = s1 * (1.f / 256.f);
            const float var = s2 * (1.f / 256.f) - mu * mu;
            stats[r] = mu;
            stats[16 + r] = rsqrtf(fmaxf(var, 0.f) + 1e-5f);
        }
    }
    __syncthreads();
    // ---- normalize + relu -> bf16 hi/lo h; stage G chunk 0 ----
    {
        const float g = ln_g[tid], bb = ln_b[tid], bias = b1[tid];
        #pragma unroll
        for (int r = 0; r < ROWS; r++) {
            const float raw = dh[r * DH + tid] + bias;
            const float v = fmaxf((raw - stats[r]) * stats[16 + r] * g + bb, 0.f);
            const __nv_bfloat16 hi = __float2bfloat16(v);
            hhi[r * LDH + tid] = hi;
            hlo[r * LDH + tid] = __float2bfloat16(v - __bfloat162float(hi));
        }
        const int r4 = tid >> 4, c4 = tid & 15;
        ((uint4*)Bhi)[r4 * 17 + c4] = ((const uint4*)Ghi_g)[tid];
        ((uint4*)Blo)[r4 * 17 + c4] = ((const uint4*)Glo_g)[tid];
    }
    __syncthreads();

    // ---- logits GEMM: 16 k-chunks, single-bar pipeline ----
    {
        const int n0 = wid * 16;
        const int r4 = tid >> 4, c4 = tid & 15;
        wmma::fragment<wmma::matrix_a, 16, 16, 16, __nv_bfloat16, wmma::row_major> fah, fal;
        wmma::fragment<wmma::matrix_b, 16, 16, 16, __nv_bfloat16, wmma::row_major> fbh, fbl;
        wmma::fragment<wmma::accumulator, 16, 16, 16, float> cl;
        wmma::fill_fragment(cl, 0.f);
        uint4 qh = ((const uint4*)Ghi_g)[256 + tid];
        uint4 ql = ((const uint4*)Glo_g)[256 + tid];
        for (int kc = 0; kc < 16; kc++) {
            const int s = kc & 1;
            if (kc < 15) {
                ((uint4*)(Bhi + (s ^ 1) * GCH))[r4 * 17 + c4] = qh;
                ((uint4*)(Blo + (s ^ 1) * GCH))[r4 * 17 + c4] = ql;
            }
            if (kc < 14) {
                qh = ((const uint4*)Ghi_g)[(kc + 2) * 256 + tid];
                ql = ((const uint4*)Glo_g)[(kc + 2) * 256 + tid];
            }
            wmma::load_matrix_sync(fah, hhi + kc * 16, LDH);
            wmma::load_matrix_sync(fal, hlo + kc * 16, LDH);
            wmma::load_matrix_sync(fbh, Bhi + s * GCH + n0, LDG2);
            wmma::load_matrix_sync(fbl, Blo + s * GCH + n0, LDG2);
            wmma::mma_sync(cl, fah, fbh, cl);
            wmma::mma_sync(cl, fah, fbl, cl);
            wmma::mma_sync(cl, fal, fbh, cl);
            __syncthreads();
        }
        wmma::store_matrix_sync(lgt + n0, cl, 128, wmma::mem_row_major);
    }
    __syncthreads();

    // ---- softmax over protos, weight mixing, action softmax (warp/row) ----
    for (int rr = 0; rr < 2; rr++) {
        const int r = wid + rr * 8;
        const int n = lane & 15;
        const int mh = lane >> 4;
        float wot = 0.f;
        #pragma unroll
        for (int mm = 0; mm < 4; mm++) {
            const int m = mm * 2 + mh;
            const float v = lgt[r * 128 + m * 16 + n] + c_g[m * 16 + n] + dds[r * 16 + n];
            float mx = v;
            #pragma unroll
            for (int m2 = 8; m2 >= 1; m2 >>= 1) mx = fmaxf(mx, __shfl_xor_sync(FULL, mx, m2));
            const float e = expf(v - mx);
            float s = e;
            #pragma unroll
            for (int m2 = 8; m2 >= 1; m2 >>= 1) s += __shfl_xor_sync(FULL, s, m2);
            wot += e / s;
        }
        wot += __shfl_xor_sync(FULL, wot, 16);
        wot *= 0.125f;

        const float f = fitness[(b0 + r) * 16 + n];
        float wr = w_prev[n] * expf(0.1f * f);
        float swr = wr;
        #pragma unroll
        for (int m2 = 8; m2 >= 1; m2 >>= 1) swr += __shfl_xor_sync(FULL, swr, m2);
        wr /= (swr + 1e-8f);

        const float crisis = stats[32 + r];
        const float alpha = 0.06f + 0.24f * (1.f - crisis);
        float w = alpha * wot + (1.f - alpha) * wr;
        float sw = w;
        #pragma unroll
        for (int m2 = 8; m2 >= 1; m2 >>= 1) sw += __shfl_xor_sync(FULL, sw, m2);
        w /= (sw + 1e-8f);
        if (lane < 16) dds[r * 16 + n] = w;
        __syncwarp();

        float mix = __int_as_float(0xff800000);
        if (lane < 30) {
            mix = 1.f;
            #pragma unroll
            for (int m = 0; m < 16; m++) mix += dds[r * 16 + m] * concs[m * 30 + lane];
        }
        float mx = mix;
        #pragma unroll
        for (int m2 = 16; m2 >= 1; m2 >>= 1) mx = fmaxf(mx, __shfl_xor_sync(FULL, mx, m2));
        float e = (lane < 30) ? expf(mix - mx) : 0.f;
        float s = e;
        #pragma unroll
        for (int m2 = 16; m2 >= 1; m2 >>= 1) s += __shfl_xor_sync(FULL, s, m2);
        float p = e / s;
        float sp = p;
        #pragma unroll
        for (int m2 = 16; m2 >= 1; m2 >>= 1) sp += __shfl_xor_sync(FULL, sp, m2);
        p = p / (sp + 1e-8f);
        if (lane < 30) out[(b0 + r) * 30 + lane] = p;
    }
}

// ---------------------------------------------------------------------------
extern "C" void kernel_launch(void* const* d_in, const int* in_sizes, int n_in,
                              void* d_out, int out_size) {
    const float* state   = (const float*)d_in[0];
    const float* fitness = (const float*)d_in[1];
    const float* pk      = (const float*)d_in[2];
    const float* W1      = (const float*)d_in[3];
    const float* b1      = (const float*)d_in[4];
    const float* ln_g    = (const float*)d_in[5];
    const float* ln_b    = (const float*)d_in[6];
    const float* W2      = (const float*)d_in[7];
    const float* b2      = (const float*)d_in[8];
    const float* dW1     = (const float*)d_in[9];
    const float* db1     = (const float*)d_in[10];
    const float* dW2     = (const float*)d_in[11];
    const float* db2     = (const float*)d_in[12];
    const float* tcW     = (const float*)d_in[13];
    const float* tcb     = (const float*)d_in[14];
    const float* tccW    = (const float*)d_in[15];
    const float* tccb    = (const float*)d_in[16];
    const float* w_prev  = (const float*)d_in[19];
    float* out = (float*)d_out;

    convert_kernel<<<304, 256>>>(W1);
    precompute_kernel<<<81, 256>>>(pk, W2, b2, dW1, db1, dW2, db2);

    const int smem_bytes = 92736;
    cudaFuncSetAttribute(main_kernel, cudaFuncAttributeMaxDynamicSharedMemorySize,
                         smem_bytes);
    main_kernel<<<NBLK, NT, smem_bytes>>>(state, fitness, pk, b1, ln_g, ln_b,
                                          tcW, tcb, tccW, tccb, w_prev, out);
}

// round 16
// speedup vs baseline: 1.1158x; 1.1158x over previous
#include <cuda_runtime.h>
#include <cuda_bf16.h>
#include <mma.h>
#include <math.h>

using namespace nvcuda;

#define B_TOT 16384
#define S_DIM 300
#define A_DIM 30
#define M_PROTO 16
#define NT 256
#define ROWS 32
#define NBLK (B_TOT / ROWS)
#define DH 260
#define LDA 312      // A row stride (624B, odd*16B -> conflict-free)
#define LDB 264      // W1 chunk stride
#define LDH 264      // h stride
#define LDG2 136     // G chunk stride
#define BCH (16 * LDB)
#define GCH (16 * LDG2)

// batch-independent tables
__device__ float c_g[128];
__device__ float conc_g[M_PROTO * A_DIM];
__device__ __align__(16) __nv_bfloat16 W1hi_g[304 * 256];
__device__ __align__(16) __nv_bfloat16 W1lo_g[304 * 256];
__device__ __align__(16) __nv_bfloat16 Ghi_g[256 * 128];
__device__ __align__(16) __nv_bfloat16 Glo_g[256 * 128];

// ---------------------------------------------------------------------------
// Prep (merged): blocks 0..303 -> W1 bf16 split; 304..367 -> 4 G rows each;
//                368 -> c_g; 369..384 -> conc_g[m]
// ---------------------------------------------------------------------------
__global__ void __launch_bounds__(256) prep_kernel(
    const float* __restrict__ pk, const float* __restrict__ W1,
    const float* __restrict__ enc_W2, const float* __restrict__ enc_b2,
    const float* __restrict__ dW1, const float* __restrict__ db1,
    const float* __restrict__ dW2, const float* __restrict__ db2) {
    const int bk = blockIdx.x;
    const int t = threadIdx.x;
    if (bk < 304) {
        const int idx = bk * 256 + t;
        const int k = idx >> 8;
        const float w = (k < 300) ? W1[idx] : 0.f;
        const __nv_bfloat16 hi = __float2bfloat16(w);
        W1hi_g[idx] = hi;
        W1lo_g[idx] = __float2bfloat16(w - __bfloat162float(hi));
    } else if (bk < 368) {
        const int gb = bk - 304;
        __shared__ float w2rows[4 * 2048];
        __shared__ float pks[16 * 257];
        __shared__ float part[256];
        for (int i = t; i < 4 * 2048; i += 256)
            w2rows[i] = enc_W2[gb * 8192 + i];
        for (int i = t; i < 4096; i += 256)
            pks[(i >> 8) * 257 + (i & 255)] = pk[i];
        __syncthreads();
        const int mn = t & 127, half = t >> 7;
        const int m = mn >> 4, n = mn & 15;
        const float* pr = pks + n * 257 + half * 128;
        #pragma unroll
        for (int rr = 0; rr < 4; rr++) {
            const float* wr = w2rows + rr * 2048 + m * 256 + half * 128;
            float s = 0.f;
            #pragma unroll 8
            for (int e = 0; e < 128; e++) s += wr[e] * pr[e];
            part[t] = s;
            __syncthreads();
            if (t < 128) {
                const float g = (part[t] + part[t + 128]) * 0.0625f;
                const int k = gb * 4 + rr;
                const __nv_bfloat16 hi = __float2bfloat16(g);
                Ghi_g[k * 128 + t] = hi;
                Glo_g[k * 128 + t] = __float2bfloat16(g - __bfloat162float(hi));
            }
            __syncthreads();
        }
    } else if (bk == 368) {
        __shared__ float part[256];
        const int mn = t & 127, half = t >> 7;
        const int m = mn >> 4, n = mn & 15;
        const float4* br = (const float4*)(enc_b2 + m * 256 + half * 128);
        const float4* pr = (const float4*)(pk + n * 256 + half * 128);
        float s = 0.f;
        #pragma unroll 8
        for (int e = 0; e < 32; e++) {
            const float4 b4 = __ldg(&br[e]);
            const float4 p4 = __ldg(&pr[e]);
            s += b4.x * p4.x + b4.y * p4.y + b4.z * p4.z + b4.w * p4.w;
        }
        part[t] = s;
        __syncthreads();
        if (t < 128) c_g[t] = (part[t] + part[t + 128]) * 0.0625f;
    } else {
        const int m = bk - 369;
        __shared__ float part[256];
        __shared__ float hd[128];
        const int h = t & 127, eh = t >> 7;
        const float* pkm = pk + m * 256 + eh * 128;
        const float* wcol = dW1 + (m * 256 + eh * 128) * 128 + h;
        float s = 0.f;
        #pragma unroll 8
        for (int e = 0; e < 128; e++) s += pkm[e] * wcol[e * 128];
        part[t] = s;
        __syncthreads();
        if (t < 128)
            hd[t] = fmaxf(part[t] + part[t + 128] + db1[m * 128 + t], 0.f);
        __syncthreads();
        if (t < A_DIM) {
            float s2 = db2[m * A_DIM + t];
            const float* w2 = dW2 + m * 128 * A_DIM + t;
            #pragma unroll 8
            for (int h2 = 0; h2 < 128; h2++)
                s2 += hd[h2] * __ldg(w2 + h2 * A_DIM);
            conc_g[m * A_DIM + t] = fmaxf(s2, 0.f) + log1pf(expf(-fabsf(s2)));
        }
    }
}

// ---------------------------------------------------------------------------
// Main kernel: 512 blocks x 256 threads, 32 batch rows/block.
// wmma bf16 hi/lo, padded strides, R14-style two-bar double buffering.
// ---------------------------------------------------------------------------
__global__ void __launch_bounds__(NT, 2) main_kernel(
    const float* __restrict__ state, const float* __restrict__ fitness,
    const float* __restrict__ pk, const float* __restrict__ b1,
    const float* __restrict__ ln_g, const float* __restrict__ ln_b,
    const float* __restrict__ tc_W, const float* __restrict__ tc_b,
    const float* __restrict__ tc_cW, const float* __restrict__ tc_cb,
    const float* __restrict__ w_prev, float* __restrict__ out) {
    extern __shared__ char smraw[];
    float* dh          = (float*)smraw;                     // 32x260 f (33280B)
    __nv_bfloat16* Ahi = (__nv_bfloat16*)(smraw + 33280);   // 32xLDA (19968B)
    __nv_bfloat16* Alo = (__nv_bfloat16*)(smraw + 53248);
    __nv_bfloat16* Bhi = (__nv_bfloat16*)(smraw + 73216);   // 2xBCH (16896B)
    __nv_bfloat16* Blo = (__nv_bfloat16*)(smraw + 90112);
    float* dds         = (float*)(smraw + 107008);          // 32x16 f
    float* concs       = (float*)(smraw + 109056);          // 480 f
    float* stats       = (float*)(smraw + 110976);          // 96 f
    float* lgt         = dh;        // alias: 32x128 f (dh dead by then)
    __nv_bfloat16* hhi = Ahi;       // alias, stride LDH
    __nv_bfloat16* hlo = Alo;

    const int tid = threadIdx.x;
    const int lane = tid & 31;
    const int wid = tid >> 5;
    const int b0 = blockIdx.x * ROWS;
    const unsigned FULL = 0xffffffffu;

    // ---- concs load + A split straight from global (no fp32 st buffer) ----
    for (int i = tid; i < M_PROTO * A_DIM; i += NT) concs[i] = conc_g[i];
    for (int i = tid; i < ROWS * LDA; i += NT) {
        const int r = i / LDA, k = i - r * LDA;
        const float v = (k < 300) ? __ldg(state + (size_t)(b0 + r) * S_DIM + k) : 0.f;
        const __nv_bfloat16 hi = __float2bfloat16(v);
        Ahi[i] = hi;
        Alo[i] = __float2bfloat16(v - __bfloat162float(hi));
    }

    // ---- stage 1: market features + danger + crisis (2 passes x 2 rows) ----
    for (int pp = 0; pp < 2; pp++) {
        const int rA = wid + pp * 16, rB = rA + 8;
        const float* sA = state + (size_t)(b0 + rA) * S_DIM;
        const float* sB = state + (size_t)(b0 + rB) * S_DIM;
        float mfa[12], mfb[12];
        #pragma unroll
        for (int pass = 0; pass < 2; pass++) {
            const float* srow = pass ? sB : sA;
            float* mf = pass ? mfb : mfa;
            float p = 0.f, sh = 0.f;
            if (lane < 30) { p = __ldg(srow + 1 + lane); sh = __ldg(srow + 31 + lane); }
            float sp = p, spp = p * p, sps = p * sh;
            #pragma unroll
            for (int m2 = 16; m2 >= 1; m2 >>= 1) {
                sp  += __shfl_xor_sync(FULL, sp, m2);
                spp += __shfl_xor_sync(FULL, spp, m2);
                sps += __shfl_xor_sync(FULL, sps, m2);
            }
            const float bal = __ldg(srow);
            const float mean = sp * (1.f / 30.f);
            const float var = fmaxf((spp - 30.f * mean * mean) * (1.f / 29.f), 0.f);
            mf[0] = bal; mf[1] = mean;
            mf[2] = sqrtf(var) + 1e-8f;
            mf[3] = bal / (bal + sps + 1e-8f);
            #pragma unroll
            for (int i = 0; i < 8; i++) mf[4 + i] = __ldg(srow + 61 + 30 * i);
        }
        float cpA = 0.f, cpB = 0.f;
        #pragma unroll
        for (int i = 0; i < 8; i++) {
            const int j = lane + 32 * i;
            const float bj = tc_b[j];
            float aA = bj, aB = bj;
            #pragma unroll
            for (int f = 0; f < 12; f++) {
                const float w = tc_W[f * 256 + j];
                aA += mfa[f] * w; aB += mfb[f] * w;
            }
            const float dA = tanhf(aA), dB = tanhf(aB);
            dh[rA * DH + j] = dA;
            dh[rB * DH + j] = dB;
            const float cw = tc_cW[j];
            cpA += dA * cw; cpB += dB * cw;
        }
        #pragma unroll
        for (int m2 = 16; m2 >= 1; m2 >>= 1) {
            cpA += __shfl_xor_sync(FULL, cpA, m2);
            cpB += __shfl_xor_sync(FULL, cpB, m2);
        }
        if (lane == 0) {
            const float cb = tc_cb[0];
            stats[64 + rA] = 1.f / (1.f + expf(-(cpA + cb)));
            stats[64 + rB] = 1.f / (1.f + expf(-(cpB + cb)));
        }
    }
    __syncthreads();

    // ---- dd[r][n] (fp32 exact) + W1 chunk-0 staging ----
    {
        const int n = tid >> 4, kq = tid & 15;
        float pkc[16];
        {
            const float4* pr = (const float4*)(pk + n * 256 + kq * 16);
            #pragma unroll
            for (int i = 0; i < 4; i++) {
                const float4 p4 = __ldg(&pr[i]);
                pkc[i * 4 + 0] = p4.x; pkc[i * 4 + 1] = p4.y;
                pkc[i * 4 + 2] = p4.z; pkc[i * 4 + 3] = p4.w;
            }
        }
        #pragma unroll 4
        for (int r = 0; r < ROWS; r++) {
            const float* dr = dh + r * DH + kq * 16;
            float s = 0.f;
            #pragma unroll
            for (int i = 0; i < 4; i++) {
                const float4 d4 = *(const float4*)&dr[i * 4];
                s += d4.x * pkc[i * 4] + d4.y * pkc[i * 4 + 1] +
                     d4.z * pkc[i * 4 + 2] + d4.w * pkc[i * 4 + 3];
            }
            #pragma unroll
            for (int m2 = 8; m2 >= 1; m2 >>= 1) s += __shfl_xor_sync(FULL, s, m2);
            if (kq == 0) dds[r * 16 + n] = s * 0.0625f;
        }
        // stage W1 chunk 0 into buffer 0
        const uint4 h0 = ((const uint4*)W1hi_g)[tid];
        const uint4 h1 = ((const uint4*)W1hi_g)[tid + 256];
        const uint4 l0 = ((const uint4*)W1lo_g)[tid];
        const uint4 l1 = ((const uint4*)W1lo_g)[tid + 256];
        const int r8 = tid >> 5, c8 = tid & 31;
        uint4* bh4 = (uint4*)Bhi;
        uint4* bl4 = (uint4*)Blo;
        bh4[r8 * 33 + c8] = h0; bh4[(r8 + 8) * 33 + c8] = h1;
        bl4[r8 * 33 + c8] = l0; bl4[(r8 + 8) * 33 + c8] = l1;
    }
    __syncthreads();

    // ---- W1 GEMM: M=32 (2 M-tiles), N=32/warp (2 N-tiles), 19 k-chunks ----
    {
        const int n0 = wid * 32;
        const int r8 = tid >> 5, c8 = tid & 31;
        wmma::fragment<wmma::matrix_a, 16, 16, 16, __nv_bfloat16, wmma::row_major> fah[2], fal[2];
        wmma::fragment<wmma::matrix_b, 16, 16, 16, __nv_bfloat16, wmma::row_major> fbh[2], fbl[2];
        wmma::fragment<wmma::accumulator, 16, 16, 16, float> acc[2][2];
        #pragma unroll
        for (int m = 0; m < 2; m++)
            #pragma unroll
            for (int n = 0; n < 2; n++) wmma::fill_fragment(acc[m][n], 0.f);
        uint4 ph0, ph1, pl0, pl1;
        for (int kc = 0; kc < 19; kc++) {
            const int s = kc & 1;
            if (kc < 18) {   // LDG chunk kc+1 into regs (overlaps mma below)
                const int base = (kc + 1) * 512;
                ph0 = ((const uint4*)W1hi_g)[base + tid];
                ph1 = ((const uint4*)W1hi_g)[base + 256 + tid];
                pl0 = ((const uint4*)W1lo_g)[base + tid];
                pl1 = ((const uint4*)W1lo_g)[base + 256 + tid];
            }
            const __nv_bfloat16* bsh = Bhi + s * BCH;
            const __nv_bfloat16* bsl = Blo + s * BCH;
            #pragma unroll
            for (int m = 0; m < 2; m++) {
                wmma::load_matrix_sync(fah[m], Ahi + m * 16 * LDA + kc * 16, LDA);
                wmma::load_matrix_sync(fal[m], Alo + m * 16 * LDA + kc * 16, LDA);
            }
            #pragma unroll
            for (int n = 0; n < 2; n++) {
                wmma::load_matrix_sync(fbh[n], bsh + n0 + n * 16, LDB);
                wmma::load_matrix_sync(fbl[n], bsl + n0 + n * 16, LDB);
            }
            #pragma unroll
            for (int m = 0; m < 2; m++)
                #pragma unroll
                for (int n = 0; n < 2; n++) {
                    wmma::mma_sync(acc[m][n], fah[m], fbh[n], acc[m][n]);
                    wmma::mma_sync(acc[m][n], fah[m], fbl[n], acc[m][n]);
                    wmma::mma_sync(acc[m][n], fal[m], fbh[n], acc[m][n]);
                }
            __syncthreads();
            if (kc < 18) {
                uint4* bh4 = (uint4*)(Bhi + (s ^ 1) * BCH);
                uint4* bl4 = (uint4*)(Blo + (s ^ 1) * BCH);
                bh4[r8 * 33 + c8] = ph0; bh4[(r8 + 8) * 33 + c8] = ph1;
                bl4[r8 * 33 + c8] = pl0; bl4[(r8 + 8) * 33 + c8] = pl1;
            }
            __syncthreads();
        }
        #pragma unroll
        for (int m = 0; m < 2; m++)
            #pragma unroll
            for (int n = 0; n < 2; n++)
                wmma::store_matrix_sync(dh + m * 16 * DH + n0 + n * 16,
                                        acc[m][n], DH, wmma::mem_row_major);
    }
    __syncthreads();

    // ---- layernorm stats (b1 folded at read), 4 rows per warp ----
    for (int rr = 0; rr < 4; rr++) {
        const int r = wid + rr * 8;
        float s1 = 0.f, s2 = 0.f;
        #pragma unroll
        for (int i = 0; i < 8; i++) {
            const int j = lane + 32 * i;
            const float v = dh[r * DH + j] + b1[j];
            s1 += v; s2 += v * v;
        }
        #pragma unroll
        for (int m2 = 16; m2 >= 1; m2 >>= 1) {
            s1 += __shfl_xor_sync(FULL, s1, m2);
            s2 += __shfl_xor_sync(FULL, s2, m2);
        }
        if (lane == 0) {
            const float mu = s1 * (1.f / 256.f);
            const float var = s2 * (1.f / 256.f) - mu * mu;
            stats[r] = mu;
            stats[32 + r] = rsqrtf(fmaxf(var, 0.f) + 1e-5f);
        }
    }
    __syncthreads();
    // ---- normalize + relu -> bf16 hi/lo h; stage G chunk 0 ----
    {
        const float g = ln_g[tid], bb = ln_b[tid], bias = b1[tid];
        #pragma unroll 4
        for (int r = 0; r < ROWS; r++) {
            const float raw = dh[r * DH + tid] + bias;
            const float v = fmaxf((raw - stats[r]) * stats[32 + r] * g + bb, 0.f);
            const __nv_bfloat16 hi = __float2bfloat16(v);
            hhi[r * LDH + tid] = hi;
            hlo[r * LDH + tid] = __float2bfloat16(v - __bfloat162float(hi));
        }
        const int r4 = tid >> 4, c4 = tid & 15;
        ((uint4*)Bhi)[r4 * 17 + c4] = ((const uint4*)Ghi_g)[tid];
        ((uint4*)Blo)[r4 * 17 + c4] = ((const uint4*)Glo_g)[tid];
    }
    __syncthreads();

    // ---- logits GEMM: M=32 (2 M-tiles), N=16/warp, 16 k-chunks ----
    {
        const int n0 = wid * 16;
        const int r4 = tid >> 4, c4 = tid & 15;
        wmma::fragment<wmma::matrix_a, 16, 16, 16, __nv_bfloat16, wmma::row_major> fah[2], fal[2];
        wmma::fragment<wmma::matrix_b, 16, 16, 16, __nv_bfloat16, wmma::row_major> fbh, fbl;
        wmma::fragment<wmma::accumulator, 16, 16, 16, float> cl[2];
        wmma::fill_fragment(cl[0], 0.f);
        wmma::fill_fragment(cl[1], 0.f);
        uint4 qh, ql;
        for (int kc = 0; kc < 16; kc++) {
            const int s = kc & 1;
            if (kc < 15) {
                qh = ((const uint4*)Ghi_g)[(kc + 1) * 256 + tid];
                ql = ((const uint4*)Glo_g)[(kc + 1) * 256 + tid];
            }
            #pragma unroll
            for (int m = 0; m < 2; m++) {
                wmma::load_matrix_sync(fah[m], hhi + m * 16 * LDH + kc * 16, LDH);
                wmma::load_matrix_sync(fal[m], hlo + m * 16 * LDH + kc * 16, LDH);
            }
            wmma::load_matrix_sync(fbh, Bhi + s * GCH + n0, LDG2);
            wmma::load_matrix_sync(fbl, Blo + s * GCH + n0, LDG2);
            #pragma unroll
            for (int m = 0; m < 2; m++) {
                wmma::mma_sync(cl[m], fah[m], fbh, cl[m]);
                wmma::mma_sync(cl[m], fah[m], fbl, cl[m]);
                wmma::mma_sync(cl[m], fal[m], fbh, cl[m]);
            }
            __syncthreads();
            if (kc < 15) {
                ((uint4*)(Bhi + (s ^ 1) * GCH))[r4 * 17 + c4] = qh;
                ((uint4*)(Blo + (s ^ 1) * GCH))[r4 * 17 + c4] = ql;
            }
            __syncthreads();
        }
        #pragma unroll
        for (int m = 0; m < 2; m++)
            wmma::store_matrix_sync(lgt + m * 16 * 128 + n0, cl[m], 128,
                                    wmma::mem_row_major);
    }
    __syncthreads();

    // ---- softmax over protos, weight mixing, action softmax (4 rows/warp) ----
    for (int rr = 0; rr < 4; rr++) {
        const int r = wid + rr * 8;
        const int n = lane & 15;
        const int mh = lane >> 4;
        float wot = 0.f;
        #pragma unroll
        for (int mm = 0; mm < 4; mm++) {
            const int m = mm * 2 + mh;
            const float v = lgt[r * 128 + m * 16 + n] + c_g[m * 16 + n] + dds[r * 16 + n];
            float mx = v;
            #pragma unroll
            for (int m2 = 8; m2 >= 1; m2 >>= 1) mx = fmaxf(mx, __shfl_xor_sync(FULL, mx, m2));
            const float e = expf(v - mx);
            float s = e;
            #pragma unroll
            for (int m2 = 8; m2 >= 1; m2 >>= 1) s += __shfl_xor_sync(FULL, s, m2);
            wot += e / s;
        }
        wot += __shfl_xor_sync(FULL, wot, 16);
        wot *= 0.125f;

        const float f = fitness[(b0 + r) * 16 + n];
        float wr = w_prev[n] * expf(0.1f * f);
        float swr = wr;
        #pragma unroll
        for (int m2 = 8; m2 >= 1; m2 >>= 1) swr += __shfl_xor_sync(FULL, swr, m2);
        wr /= (swr + 1e-8f);

        const float crisis = stats[64 + r];
        const float alpha = 0.06f + 0.24f * (1.f - crisis);
        float w = alpha * wot + (1.f - alpha) * wr;
        float sw = w;
        #pragma unroll
        for (int m2 = 8; m2 >= 1; m2 >>= 1) sw += __shfl_xor_sync(FULL, sw, m2);
        w /= (sw + 1e-8f);
        if (lane < 16) dds[r * 16 + n] = w;
        __syncwarp();

        float mix = __int_as_float(0xff800000);
        if (lane < 30) {
            mix = 1.f;
            #pragma unroll
            for (int m = 0; m < 16; m++) mix += dds[r * 16 + m] * concs[m * 30 + lane];
        }
        float mx = mix;
        #pragma unroll
        for (int m2 = 16; m2 >= 1; m2 >>= 1) mx = fmaxf(mx, __shfl_xor_sync(FULL, mx, m2));
        float e = (lane < 30) ? expf(mix - mx) : 0.f;
        float s = e;
        #pragma unroll
        for (int m2 = 16; m2 >= 1; m2 >>= 1) s += __shfl_xor_sync(FULL, s, m2);
        float p = e / s;
        float sp = p;
        #pragma unroll
        for (int m2 = 16; m2 >= 1; m2 >>= 1) sp += __shfl_xor_sync(FULL, sp, m2);
        p = p / (sp + 1e-8f);
        if (lane < 30) out[(b0 + r) * 30 + lane] = p;
    }
}

// ---------------------------------------------------------------------------
extern "C" void kernel_launch(void* const* d_in, const int* in_sizes, int n_in,
                              void* d_out, int out_size) {
    const float* state   = (const float*)d_in[0];
    const float* fitness = (const float*)d_in[1];
    const float* pk      = (const float*)d_in[2];
    const float* W1      = (const float*)d_in[3];
    const float* b1      = (const float*)d_in[4];
    const float* ln_g    = (const float*)d_in[5];
    const float* ln_b    = (const float*)d_in[6];
    const float* W2      = (const float*)d_in[7];
    const float* b2      = (const float*)d_in[8];
    const float* dW1     = (const float*)d_in[9];
    const float* db1     = (const float*)d_in[10];
    const float* dW2     = (const float*)d_in[11];
    const float* db2     = (const float*)d_in[12];
    const float* tcW     = (const float*)d_in[13];
    const float* tcb     = (const float*)d_in[14];
    const float* tccW    = (const float*)d_in[15];
    const float* tccb    = (const float*)d_in[16];
    const float* w_prev  = (const float*)d_in[19];
    float* out = (float*)d_out;

    prep_kernel<<<385, 256>>>(pk, W1, W2, b2, dW1, db1, dW2, db2);

    const int smem_bytes = 111360;
    cudaFuncSetAttribute(main_kernel, cudaFuncAttributeMaxDynamicSharedMemorySize,
                         smem_bytes);
    main_kernel<<<NBLK, NT, smem_bytes>>>(state, fitness, pk, b1, ln_g, ln_b,
                                          tcW, tcb, tccW, tccb, w_prev, out);
}

// round 17
// speedup vs baseline: 1.2725x; 1.1404x over previous
#include <cuda_runtime.h>
#include <cuda_bf16.h>
#include <cuda_pipeline.h>
#include <mma.h>
#include <math.h>

using namespace nvcuda;

#define B_TOT 16384
#define S_DIM 300
#define A_DIM 30
#define M_PROTO 16
#define NT 256
#define ROWS 32
#define NBLK (B_TOT / ROWS)
#define DH 260
#define LDA 312
#define LDB 264
#define LDH 264
#define LDG2 136
#define BCH (16 * LDB)
#define GCH (16 * LDG2)

// batch-independent tables
__device__ float c_g[128];
__device__ float conc_g[M_PROTO * A_DIM];
__device__ __align__(16) __nv_bfloat16 W1hi_g[304 * 256];
__device__ __align__(16) __nv_bfloat16 W1lo_g[304 * 256];
__device__ __align__(16) __nv_bfloat16 Ghi_g[256 * 128];
__device__ __align__(16) __nv_bfloat16 Glo_g[256 * 128];

__device__ __forceinline__ float ftanh(float x) {
    const float e = __expf(2.f * x);
    return 1.f - __fdividef(2.f, e + 1.f);
}

// ---------------------------------------------------------------------------
// Prep: 0..303 -> W1 split; 304..367 -> 4 G rows; 368 -> c_g; 369..384 -> conc
// ---------------------------------------------------------------------------
__global__ void __launch_bounds__(256) prep_kernel(
    const float* __restrict__ pk, const float* __restrict__ W1,
    const float* __restrict__ enc_W2, const float* __restrict__ enc_b2,
    const float* __restrict__ dW1, const float* __restrict__ db1,
    const float* __restrict__ dW2, const float* __restrict__ db2) {
    const int bk = blockIdx.x;
    const int t = threadIdx.x;
    if (bk < 304) {
        const int idx = bk * 256 + t;
        const int k = idx >> 8;
        const float w = (k < 300) ? W1[idx] : 0.f;
        const __nv_bfloat16 hi = __float2bfloat16(w);
        W1hi_g[idx] = hi;
        W1lo_g[idx] = __float2bfloat16(w - __bfloat162float(hi));
    } else if (bk < 368) {
        const int gb = bk - 304;
        __shared__ float w2rows[4 * 2048];
        __shared__ float pks[16 * 257];
        __shared__ float part[256];
        for (int i = t; i < 4 * 2048; i += 256)
            w2rows[i] = enc_W2[gb * 8192 + i];
        for (int i = t; i < 4096; i += 256)
            pks[(i >> 8) * 257 + (i & 255)] = pk[i];
        __syncthreads();
        const int mn = t & 127, half = t >> 7;
        const int m = mn >> 4, n = mn & 15;
        const float* pr = pks + n * 257 + half * 128;
        #pragma unroll
        for (int rr = 0; rr < 4; rr++) {
            const float* wr = w2rows + rr * 2048 + m * 256 + half * 128;
            float s = 0.f;
            #pragma unroll 8
            for (int e = 0; e < 128; e++) s += wr[e] * pr[e];
            part[t] = s;
            __syncthreads();
            if (t < 128) {
                const float g = (part[t] + part[t + 128]) * 0.0625f;
                const int k = gb * 4 + rr;
                const __nv_bfloat16 hi = __float2bfloat16(g);
                Ghi_g[k * 128 + t] = hi;
                Glo_g[k * 128 + t] = __float2bfloat16(g - __bfloat162float(hi));
            }
            __syncthreads();
        }
    } else if (bk == 368) {
        __shared__ float part[256];
        const int mn = t & 127, half = t >> 7;
        const int m = mn >> 4, n = mn & 15;
        const float4* br = (const float4*)(enc_b2 + m * 256 + half * 128);
        const float4* pr = (const float4*)(pk + n * 256 + half * 128);
        float s = 0.f;
        #pragma unroll 8
        for (int e = 0; e < 32; e++) {
            const float4 b4 = __ldg(&br[e]);
            const float4 p4 = __ldg(&pr[e]);
            s += b4.x * p4.x + b4.y * p4.y + b4.z * p4.z + b4.w * p4.w;
        }
        part[t] = s;
        __syncthreads();
        if (t < 128) c_g[t] = (part[t] + part[t + 128]) * 0.0625f;
    } else {
        const int m = bk - 369;
        __shared__ float part[256];
        __shared__ float hd[128];
        const int h = t & 127, eh = t >> 7;
        const float* pkm = pk + m * 256 + eh * 128;
        const float* wcol = dW1 + (m * 256 + eh * 128) * 128 + h;
        float s = 0.f;
        #pragma unroll 8
        for (int e = 0; e < 128; e++) s += pkm[e] * wcol[e * 128];
        part[t] = s;
        __syncthreads();
        if (t < 128)
            hd[t] = fmaxf(part[t] + part[t + 128] + db1[m * 128 + t], 0.f);
        __syncthreads();
        if (t < A_DIM) {
            float s2 = db2[m * A_DIM + t];
            const float* w2 = dW2 + m * 128 * A_DIM + t;
            #pragma unroll 8
            for (int h2 = 0; h2 < 128; h2++)
                s2 += hd[h2] * __ldg(w2 + h2 * A_DIM);
            conc_g[m * A_DIM + t] = fmaxf(s2, 0.f) + log1pf(expf(-fabsf(s2)));
        }
    }
}

// ---------------------------------------------------------------------------
// Main kernel: 512 blocks x 256 threads, 32 batch rows/block.
// ---------------------------------------------------------------------------
__global__ void __launch_bounds__(NT, 2) main_kernel(
    const float* __restrict__ state, const float* __restrict__ fitness,
    const float* __restrict__ pk, const float* __restrict__ b1,
    const float* __restrict__ ln_g, const float* __restrict__ ln_b,
    const float* __restrict__ tc_W, const float* __restrict__ tc_b,
    const float* __restrict__ tc_cW, const float* __restrict__ tc_cb,
    const float* __restrict__ w_prev, float* __restrict__ out) {
    extern __shared__ char smraw[];
    float* dh          = (float*)smraw;                     // 32x260 f
    __nv_bfloat16* Ahi = (__nv_bfloat16*)(smraw + 33280);   // 32xLDA
    __nv_bfloat16* Alo = (__nv_bfloat16*)(smraw + 53248);
    __nv_bfloat16* Bhi = (__nv_bfloat16*)(smraw + 73216);   // 2xBCH
    __nv_bfloat16* Blo = (__nv_bfloat16*)(smraw + 90112);
    float* dds         = (float*)(smraw + 107008);          // 32x16 f
    float* concs       = (float*)(smraw + 109056);          // 480 f
    float* stats       = (float*)(smraw + 110976);          // 96 f
    float* lgt         = dh;
    __nv_bfloat16* hhi = Ahi;
    __nv_bfloat16* hlo = Alo;

    const int tid = threadIdx.x;
    const int lane = tid & 31;
    const int wid = tid >> 5;
    const int b0 = blockIdx.x * ROWS;
    const unsigned FULL = 0xffffffffu;

    // ---- concs + A split (packed bf16x2 stores) ----
    for (int i = tid; i < M_PROTO * A_DIM; i += NT) concs[i] = conc_g[i];
    for (int i = tid; i < (ROWS * LDA) / 2; i += NT) {
        const int j = i * 2;
        const int r = j / LDA, k = j - r * LDA;
        float v0 = 0.f, v1 = 0.f;
        if (k + 1 < 300) {
            const float2 s2 = *(const float2*)(state + (size_t)(b0 + r) * S_DIM + k);
            v0 = s2.x; v1 = s2.y;
        }
        const __nv_bfloat162 hi2 = __floats2bfloat162_rn(v0, v1);
        const float l0 = v0 - __bfloat162float(__low2bfloat16(hi2));
        const float l1 = v1 - __bfloat162float(__high2bfloat16(hi2));
        ((__nv_bfloat162*)Ahi)[i] = hi2;
        ((__nv_bfloat162*)Alo)[i] = __floats2bfloat162_rn(l0, l1);
    }

    // ---- stage 1: market features + danger + crisis (4 rows/warp, 1 pass) ----
    {
        float mfr[4][12];
        #pragma unroll
        for (int q = 0; q < 4; q++) {
            const int r = wid + q * 8;
            const float* srow = state + (size_t)(b0 + r) * S_DIM;
            float p = 0.f, sh = 0.f;
            if (lane < 30) { p = __ldg(srow + 1 + lane); sh = __ldg(srow + 31 + lane); }
            float sp = p, spp = p * p, sps = p * sh;
            #pragma unroll
            for (int m2 = 16; m2 >= 1; m2 >>= 1) {
                sp  += __shfl_xor_sync(FULL, sp, m2);
                spp += __shfl_xor_sync(FULL, spp, m2);
                sps += __shfl_xor_sync(FULL, sps, m2);
            }
            const float bal = __ldg(srow);
            const float mean = sp * (1.f / 30.f);
            const float var = fmaxf((spp - 30.f * mean * mean) * (1.f / 29.f), 0.f);
            mfr[q][0] = bal; mfr[q][1] = mean;
            mfr[q][2] = sqrtf(var) + 1e-8f;
            mfr[q][3] = bal / (bal + sps + 1e-8f);
            #pragma unroll
            for (int i = 0; i < 8; i++) mfr[q][4 + i] = __ldg(srow + 61 + 30 * i);
        }
        float cp[4] = {0.f, 0.f, 0.f, 0.f};
        #pragma unroll
        for (int i = 0; i < 8; i++) {
            const int j = lane + 32 * i;
            const float bj = tc_b[j];
            float a[4] = {bj, bj, bj, bj};
            #pragma unroll
            for (int f = 0; f < 12; f++) {
                const float w = __ldg(tc_W + f * 256 + j);
                #pragma unroll
                for (int q = 0; q < 4; q++) a[q] += mfr[q][f] * w;
            }
            const float cw = tc_cW[j];
            #pragma unroll
            for (int q = 0; q < 4; q++) {
                const float d = ftanh(a[q]);
                dh[(wid + q * 8) * DH + j] = d;
                cp[q] += d * cw;
            }
        }
        #pragma unroll
        for (int q = 0; q < 4; q++)
            #pragma unroll
            for (int m2 = 16; m2 >= 1; m2 >>= 1)
                cp[q] += __shfl_xor_sync(FULL, cp[q], m2);
        if (lane == 0) {
            const float cb = tc_cb[0];
            #pragma unroll
            for (int q = 0; q < 4; q++)
                stats[64 + wid + q * 8] = __fdividef(1.f, 1.f + __expf(-(cp[q] + cb)));
        }
    }
    __syncthreads();

    // ---- dd[r][n] (fp32 exact) ----
    {
        const int n = tid >> 4, kq = tid & 15;
        float pkc[16];
        {
            const float4* pr = (const float4*)(pk + n * 256 + kq * 16);
            #pragma unroll
            for (int i = 0; i < 4; i++) {
                const float4 p4 = __ldg(&pr[i]);
                pkc[i * 4 + 0] = p4.x; pkc[i * 4 + 1] = p4.y;
                pkc[i * 4 + 2] = p4.z; pkc[i * 4 + 3] = p4.w;
            }
        }
        #pragma unroll 4
        for (int r = 0; r < ROWS; r++) {
            const float* dr = dh + r * DH + kq * 16;
            float s = 0.f;
            #pragma unroll
            for (int i = 0; i < 4; i++) {
                const float4 d4 = *(const float4*)&dr[i * 4];
                s += d4.x * pkc[i * 4] + d4.y * pkc[i * 4 + 1] +
                     d4.z * pkc[i * 4 + 2] + d4.w * pkc[i * 4 + 3];
            }
            #pragma unroll
            for (int m2 = 8; m2 >= 1; m2 >>= 1) s += __shfl_xor_sync(FULL, s, m2);
            if (kq == 0) dds[r * 16 + n] = s * 0.0625f;
        }
    }
    // ---- cp.async prologue: stage W1 chunks 0,1 ----
    {
        const int r8 = tid >> 5, c8 = tid & 31;
        #pragma unroll
        for (int c = 0; c < 2; c++) {
            const int base = c * 512;
            uint4* bh4 = (uint4*)(Bhi + c * BCH);
            uint4* bl4 = (uint4*)(Blo + c * BCH);
            __pipeline_memcpy_async(&bh4[r8 * 33 + c8], &((const uint4*)W1hi_g)[base + tid], 16);
            __pipeline_memcpy_async(&bh4[(r8 + 8) * 33 + c8], &((const uint4*)W1hi_g)[base + 256 + tid], 16);
            __pipeline_memcpy_async(&bl4[r8 * 33 + c8], &((const uint4*)W1lo_g)[base + tid], 16);
            __pipeline_memcpy_async(&bl4[(r8 + 8) * 33 + c8], &((const uint4*)W1lo_g)[base + 256 + tid], 16);
            __pipeline_commit();
        }
    }
    __syncthreads();

    // ---- W1 GEMM: 19 k-chunks, cp.async double buffer ----
    {
        const int n0 = wid * 32;
        const int r8 = tid >> 5, c8 = tid & 31;
        wmma::fragment<wmma::matrix_a, 16, 16, 16, __nv_bfloat16, wmma::row_major> fah[2], fal[2];
        wmma::fragment<wmma::matrix_b, 16, 16, 16, __nv_bfloat16, wmma::row_major> fbh[2], fbl[2];
        wmma::fragment<wmma::accumulator, 16, 16, 16, float> acc[2][2];
        #pragma unroll
        for (int m = 0; m < 2; m++)
            #pragma unroll
            for (int n = 0; n < 2; n++) wmma::fill_fragment(acc[m][n], 0.f);
        for (int kc = 0; kc < 19; kc++) {
            const int s = kc & 1;
            __pipeline_wait_prior(1);
            __syncthreads();
            const __nv_bfloat16* bsh = Bhi + s * BCH;
            const __nv_bfloat16* bsl = Blo + s * BCH;
            #pragma unroll
            for (int m = 0; m < 2; m++) {
                wmma::load_matrix_sync(fah[m], Ahi + m * 16 * LDA + kc * 16, LDA);
                wmma::load_matrix_sync(fal[m], Alo + m * 16 * LDA + kc * 16, LDA);
            }
            #pragma unroll
            for (int n = 0; n < 2; n++) {
                wmma::load_matrix_sync(fbh[n], bsh + n0 + n * 16, LDB);
                wmma::load_matrix_sync(fbl[n], bsl + n0 + n * 16, LDB);
            }
            #pragma unroll
            for (int m = 0; m < 2; m++)
                #pragma unroll
                for (int n = 0; n < 2; n++) {
                    wmma::mma_sync(acc[m][n], fah[m], fbh[n], acc[m][n]);
                    wmma::mma_sync(acc[m][n], fah[m], fbl[n], acc[m][n]);
                    wmma::mma_sync(acc[m][n], fal[m], fbh[n], acc[m][n]);
                }
            __syncthreads();
            if (kc + 2 < 19) {
                const int base = (kc + 2) * 512;
                uint4* bh4 = (uint4*)(Bhi + s * BCH);
                uint4* bl4 = (uint4*)(Blo + s * BCH);
                __pipeline_memcpy_async(&bh4[r8 * 33 + c8], &((const uint4*)W1hi_g)[base + tid], 16);
                __pipeline_memcpy_async(&bh4[(r8 + 8) * 33 + c8], &((const uint4*)W1hi_g)[base + 256 + tid], 16);
                __pipeline_memcpy_async(&bl4[r8 * 33 + c8], &((const uint4*)W1lo_g)[base + tid], 16);
                __pipeline_memcpy_async(&bl4[(r8 + 8) * 33 + c8], &((const uint4*)W1lo_g)[base + 256 + tid], 16);
            }
            __pipeline_commit();
        }
        #pragma unroll
        for (int m = 0; m < 2; m++)
            #pragma unroll
            for (int n = 0; n < 2; n++)
                wmma::store_matrix_sync(dh + m * 16 * DH + n0 + n * 16,
                                        acc[m][n], DH, wmma::mem_row_major);
    }
    __syncthreads();

    // ---- layernorm stats (b1 folded at read), 4 rows per warp ----
    for (int rr = 0; rr < 4; rr++) {
        const int r = wid + rr * 8;
        float s1 = 0.f, s2 = 0.f;
        #pragma unroll
        for (int i = 0; i < 8; i++) {
            const int j = lane + 32 * i;
            const float v = dh[r * DH + j] + b1[j];
            s1 += v; s2 += v * v;
        }
        #pragma unroll
        for (int m2 = 16; m2 >= 1; m2 >>= 1) {
            s1 += __shfl_xor_sync(FULL, s1, m2);
            s2 += __shfl_xor_sync(FULL, s2, m2);
        }
        if (lane == 0) {
            const float mu = s1 * (1.f / 256.f);
            const float var = s2 * (1.f / 256.f) - mu * mu;
            stats[r] = mu;
            stats[32 + r] = rsqrtf(fmaxf(var, 0.f) + 1e-5f);
        }
    }
    __syncthreads();
    // ---- normalize + relu -> bf16 hi/lo h (packed pair stores over j) ----
    {
        const int j0 = (tid & 127) * 2;           // column pair
        const int rh = tid >> 7;                  // row half (0/1)
        const float g0 = ln_g[j0], g1 = ln_g[j0 + 1];
        const float bb0 = ln_b[j0], bb1 = ln_b[j0 + 1];
        const float bi0 = b1[j0], bi1 = b1[j0 + 1];
        #pragma unroll 4
        for (int rr = 0; rr < 16; rr++) {
            const int r = rh * 16 + rr;
            const float mu = stats[r], rs = stats[32 + r];
            const float v0 = fmaxf((dh[r * DH + j0] + bi0 - mu) * rs * g0 + bb0, 0.f);
            const float v1 = fmaxf((dh[r * DH + j0 + 1] + bi1 - mu) * rs * g1 + bb1, 0.f);
            const __nv_bfloat162 hi2 = __floats2bfloat162_rn(v0, v1);
            const float l0 = v0 - __bfloat162float(__low2bfloat16(hi2));
            const float l1 = v1 - __bfloat162float(__high2bfloat16(hi2));
            ((__nv_bfloat162*)(hhi + r * LDH))[j0 >> 1] = hi2;
            ((__nv_bfloat162*)(hlo + r * LDH))[j0 >> 1] = __floats2bfloat162_rn(l0, l1);
        }
    }
    // ---- cp.async prologue: stage G chunks 0,1 ----
    {
        const int r4 = tid >> 4, c4 = tid & 15;
        #pragma unroll
        for (int c = 0; c < 2; c++) {
            __pipeline_memcpy_async(&((uint4*)(Bhi + c * GCH))[r4 * 17 + c4],
                                    &((const uint4*)Ghi_g)[c * 256 + tid], 16);
            __pipeline_memcpy_async(&((uint4*)(Blo + c * GCH))[r4 * 17 + c4],
                                    &((const uint4*)Glo_g)[c * 256 + tid], 16);
            __pipeline_commit();
        }
    }
    __syncthreads();

    // ---- logits GEMM: 16 k-chunks, cp.async double buffer ----
    {
        const int n0 = wid * 16;
        const int r4 = tid >> 4, c4 = tid & 15;
        wmma::fragment<wmma::matrix_a, 16, 16, 16, __nv_bfloat16, wmma::row_major> fah[2], fal[2];
        wmma::fragment<wmma::matrix_b, 16, 16, 16, __nv_bfloat16, wmma::row_major> fbh, fbl;
        wmma::fragment<wmma::accumulator, 16, 16, 16, float> cl[2];
        wmma::fill_fragment(cl[0], 0.f);
        wmma::fill_fragment(cl[1], 0.f);
        for (int kc = 0; kc < 16; kc++) {
            const int s = kc & 1;
            __pipeline_wait_prior(1);
            __syncthreads();
            #pragma unroll
            for (int m = 0; m < 2; m++) {
                wmma::load_matrix_sync(fah[m], hhi + m * 16 * LDH + kc * 16, LDH);
                wmma::load_matrix_sync(fal[m], hlo + m * 16 * LDH + kc * 16, LDH);
            }
            wmma::load_matrix_sync(fbh, Bhi + s * GCH + n0, LDG2);
            wmma::load_matrix_sync(fbl, Blo + s * GCH + n0, LDG2);
            #pragma unroll
            for (int m = 0; m < 2; m++) {
                wmma::mma_sync(cl[m], fah[m], fbh, cl[m]);
                wmma::mma_sync(cl[m], fah[m], fbl, cl[m]);
                wmma::mma_sync(cl[m], fal[m], fbh, cl[m]);
            }
            __syncthreads();
            if (kc + 2 < 16) {
                __pipeline_memcpy_async(&((uint4*)(Bhi + s * GCH))[r4 * 17 + c4],
                                        &((const uint4*)Ghi_g)[(kc + 2) * 256 + tid], 16);
                __pipeline_memcpy_async(&((uint4*)(Blo + s * GCH))[r4 * 17 + c4],
                                        &((const uint4*)Glo_g)[(kc + 2) * 256 + tid], 16);
            }
            __pipeline_commit();
        }
        #pragma unroll
        for (int m = 0; m < 2; m++)
            wmma::store_matrix_sync(lgt + m * 16 * 128 + n0, cl[m], 128,
                                    wmma::mem_row_major);
    }
    __syncthreads();

    // ---- softmax over protos, weight mixing, action softmax (4 rows/warp) ----
    for (int rr = 0; rr < 4; rr++) {
        const int r = wid + rr * 8;
        const int n = lane & 15;
        const int mh = lane >> 4;
        float wot = 0.f;
        #pragma unroll
        for (int mm = 0; mm < 4; mm++) {
            const int m = mm * 2 + mh;
            const float v = lgt[r * 128 + m * 16 + n] + c_g[m * 16 + n] + dds[r * 16 + n];
            float mx = v;
            #pragma unroll
            for (int m2 = 8; m2 >= 1; m2 >>= 1) mx = fmaxf(mx, __shfl_xor_sync(FULL, mx, m2));
            const float e = __expf(v - mx);
            float s = e;
            #pragma unroll
            for (int m2 = 8; m2 >= 1; m2 >>= 1) s += __shfl_xor_sync(FULL, s, m2);
            wot += __fdividef(e, s);
        }
        wot += __shfl_xor_sync(FULL, wot, 16);
        wot *= 0.125f;

        const float f = fitness[(b0 + r) * 16 + n];
        float wr = w_prev[n] * __expf(0.1f * f);
        float swr = wr;
        #pragma unroll
        for (int m2 = 8; m2 >= 1; m2 >>= 1) swr += __shfl_xor_sync(FULL, swr, m2);
        wr = __fdividef(wr, swr + 1e-8f);

        const float crisis = stats[64 + r];
        const float alpha = 0.06f + 0.24f * (1.f - crisis);
        float w = alpha * wot + (1.f - alpha) * wr;
        float sw = w;
        #pragma unroll
        for (int m2 = 8; m2 >= 1; m2 >>= 1) sw += __shfl_xor_sync(FULL, sw, m2);
        w = __fdividef(w, sw + 1e-8f);
        if (lane < 16) dds[r * 16 + n] = w;
        __syncwarp();

        float mix = __int_as_float(0xff800000);
        if (lane < 30) {
            mix = 1.f;
            #pragma unroll
            for (int m = 0; m < 16; m++) mix += dds[r * 16 + m] * concs[m * 30 + lane];
        }
        float mx = mix;
        #pragma unroll
        for (int m2 = 16; m2 >= 1; m2 >>= 1) mx = fmaxf(mx, __shfl_xor_sync(FULL, mx, m2));
        float e = (lane < 30) ? __expf(mix - mx) : 0.f;
        float s = e;
        #pragma unroll
        for (int m2 = 16; m2 >= 1; m2 >>= 1) s += __shfl_xor_sync(FULL, s, m2);
        float p = __fdividef(e, s);
        float sp = p;
        #pragma unroll
        for (int m2 = 16; m2 >= 1; m2 >>= 1) sp += __shfl_xor_sync(FULL, sp, m2);
        p = __fdividef(p, sp + 1e-8f);
        if (lane < 30) out[(b0 + r) * 30 + lane] = p;
    }
}

// ---------------------------------------------------------------------------
extern "C" void kernel_launch(void* const* d_in, const int* in_sizes, int n_in,
                              void* d_out, int out_size) {
    const float* state   = (const float*)d_in[0];
    const float* fitness = (const float*)d_in[1];
    const float* pk      = (const float*)d_in[2];
    const float* W1      = (const float*)d_in[3];
    const float* b1      = (const float*)d_in[4];
    const float* ln_g    = (const float*)d_in[5];
    const float* ln_b    = (const float*)d_in[6];
    const float* W2      = (const float*)d_in[7];
    const float* b2      = (const float*)d_in[8];
    const float* dW1     = (const float*)d_in[9];
    const float* db1     = (const float*)d_in[10];
    const float* dW2     = (const float*)d_in[11];
    const float* db2     = (const float*)d_in[12];
    const float* tcW     = (const float*)d_in[13];
    const float* tcb     = (const float*)d_in[14];
    const float* tccW    = (const float*)d_in[15];
    const float* tccb    = (const float*)d_in[16];
    const float* w_prev  = (const float*)d_in[19];
    float* out = (float*)d_out;

    prep_kernel<<<385, 256>>>(pk, W1, W2, b2, dW1, db1, dW2, db2);

    const int smem_bytes = 111360;
    cudaFuncSetAttribute(main_kernel, cudaFuncAttributeMaxDynamicSharedMemorySize,
                         smem_bytes);
    main_kernel<<<NBLK, NT, smem_bytes>>>(state, fitness, pk, b1, ln_g, ln_b,
                                          tcW, tcb, tccW, tccb, w_prev, out);
}